// round 14
// baseline (speedup 1.0000x reference)
#include <cuda_runtime.h>
#include <cuda_bf16.h>
#include <cstdint>

// ---------------------------------------------------------------------------
// BertBiAttention — round 13: GEMM warp tile 64x64 (4 warps, 128 thr, halved
// LDSM per MMA). Flash frozen at R10/R12 config. B=4,S=2048,HID=768,H=12.
// ---------------------------------------------------------------------------

constexpr int B = 4, S = 2048, HID = 768, H = 12, HD = 64;
constexpr int M = B * S;                       // 8192
constexpr size_t MAT = (size_t)M * HID;        // 6.29M elems

__device__ float g_scratch[10 * 6291456];

using bf16 = __nv_bfloat16;

__device__ __forceinline__ void cp16(void* dst_smem, const void* src) {
    uint32_t d = (uint32_t)__cvta_generic_to_shared(dst_smem);
    asm volatile("cp.async.cg.shared.global [%0], [%1], 16;" :: "r"(d), "l"(src));
}
__device__ __forceinline__ void cp_commit() { asm volatile("cp.async.commit_group;"); }
__device__ __forceinline__ void cp_wait0()  { asm volatile("cp.async.wait_group 0;"); }

__device__ __forceinline__ void mma_bf16(float c[4], const uint32_t a[4],
                                         uint32_t b0, uint32_t b1) {
    asm volatile(
        "mma.sync.aligned.m16n8k16.row.col.f32.bf16.bf16.f32 "
        "{%0,%1,%2,%3}, {%4,%5,%6,%7}, {%8,%9}, {%0,%1,%2,%3};"
        : "+f"(c[0]), "+f"(c[1]), "+f"(c[2]), "+f"(c[3])
        : "r"(a[0]), "r"(a[1]), "r"(a[2]), "r"(a[3]), "r"(b0), "r"(b1));
}

__device__ __forceinline__ uint32_t bf16pack(float hi, float lo) {
    uint32_t r;
    asm("cvt.rn.bf16x2.f32 %0, %1, %2;" : "=r"(r) : "f"(hi), "f"(lo));
    return r;
}

__device__ __forceinline__ float ex2(float x) {
    float r;
    asm("ex2.approx.ftz.f32 %0, %1;" : "=f"(r) : "f"(x));
    return r;
}

__device__ __forceinline__ void ldsm_x4(uint32_t& r0, uint32_t& r1,
                                        uint32_t& r2, uint32_t& r3,
                                        uint32_t smem_addr) {
    asm volatile("ldmatrix.sync.aligned.m8n8.x4.shared.b16 {%0,%1,%2,%3}, [%4];"
                 : "=r"(r0), "=r"(r1), "=r"(r2), "=r"(r3) : "r"(smem_addr));
}
__device__ __forceinline__ void ldsm_x4_trans(uint32_t& r0, uint32_t& r1,
                                              uint32_t& r2, uint32_t& r3,
                                              uint32_t smem_addr) {
    asm volatile("ldmatrix.sync.aligned.m8n8.x4.trans.shared.b16 {%0,%1,%2,%3}, [%4];"
                 : "=r"(r0), "=r"(r1), "=r"(r2), "=r"(r3) : "r"(smem_addr));
}

// ---------------------------------------------------------------------------
// Converters
// ---------------------------------------------------------------------------
__global__ void __launch_bounds__(256) conv_x_kernel(
    const float* __restrict__ x1, const float* __restrict__ x2,
    bf16* __restrict__ o1, bf16* __restrict__ o2)
{
    const float* x = blockIdx.y ? x2 : x1;
    bf16* o = blockIdx.y ? o2 : o1;
    const int n4 = (int)(MAT / 4);
    for (int i = blockIdx.x * 256 + threadIdx.x; i < n4; i += gridDim.x * 256) {
        float4 v = *(const float4*)(x + (size_t)i * 4);
        uint32_t lo = bf16pack(v.y, v.x);
        uint32_t hi = bf16pack(v.w, v.z);
        *(uint2*)(o + (size_t)i * 4) = make_uint2(lo, hi);
    }
}

struct WPtrs { const float* w[8]; };

// Wt[z][n][k] = bf16(W[z][k][n])
__global__ void __launch_bounds__(256) conv_wt_kernel(WPtrs wp, bf16* __restrict__ Wt) {
    __shared__ float t[32][33];
    const int z = blockIdx.z;
    const float* W = wp.w[z];
    const int k0 = blockIdx.x * 32, n0 = blockIdx.y * 32;
    const int tx = threadIdx.x & 31, ty = threadIdx.x >> 5;   // 32 x 8
#pragma unroll
    for (int r = 0; r < 4; r++)
        t[ty + r * 8][tx] = W[(size_t)(k0 + ty + r * 8) * 768 + n0 + tx];
    __syncthreads();
    bf16* O = Wt + (size_t)z * 768 * 768;
#pragma unroll
    for (int r = 0; r < 4; r++)
        O[(size_t)(n0 + ty + r * 8) * 768 + k0 + tx] =
            __float2bfloat16(t[tx][ty + r * 8]);
}

// ---------------------------------------------------------------------------
// Batched GEMM bf16: BM=128, BN=128, BK=64, 4 warps (2m x 2n), warp tile
// 64x64, 128 threads, double buffered, 2 CTA/SM. LDSM-per-MMA ratio 4.0
// (vs 2.67 at 32x64): per-iter CTA smem reads 96KB -> 64KB.
// ---------------------------------------------------------------------------
struct GemmBatch {
    const bf16* A[6]; const bf16* W[6]; const float* bias[6]; void* C[6];
};

constexpr int G_AS = 128 * 72;
constexpr int G_BS = 128 * 72;
constexpr int GEMM_SMEM = (2 * G_AS + 2 * G_BS) * 2;   // 73728 B

template <bool OUT_BF16>
__global__ void __launch_bounds__(128, 2) gemm_bf16_kernel(GemmBatch gb) {
    const int z = blockIdx.z;
    const bf16* A = gb.A[z];
    const bf16* W = gb.W[z];
    const float* bias = gb.bias[z];

    extern __shared__ __align__(16) bf16 smg[];
    bf16* As = smg;
    bf16* Bs = smg + 2 * G_AS;

    const int tid = threadIdx.x;
    const int warp = tid >> 5, lane = tid & 31;
    const int gq = lane >> 2, tq = lane & 3;
    const int wm = warp & 1, wn = warp >> 1;
    const int row0 = blockIdx.y * 128, col0 = blockIdx.x * 128;

    const int r8 = tid >> 3, c8 = (tid & 7) << 3;   // 16 rows/pass, 16B chunks

    auto load_tile = [&](int st, int k0) {
        bf16* Ab = As + st * G_AS;
        bf16* Bb = Bs + st * G_BS;
#pragma unroll
        for (int i = 0; i < 8; i++) {
            int r = r8 + i * 16;
            cp16(&Ab[r * 72 + c8], A + (size_t)(row0 + r) * 768 + k0 + c8);
            cp16(&Bb[r * 72 + c8], W + (size_t)(col0 + r) * 768 + k0 + c8);
        }
    };

    float acc[4][8][4] = {};

    load_tile(0, 0);
    cp_commit();

    for (int kt = 0; kt < 12; kt++) {
        cp_wait0();
        __syncthreads();
        if (kt + 1 < 12) {
            load_tile((kt + 1) & 1, (kt + 1) * 64);
            cp_commit();
        }
        const int st = kt & 1;
        uint32_t a_sh = (uint32_t)__cvta_generic_to_shared(As + st * G_AS);
        uint32_t b_sh = (uint32_t)__cvta_generic_to_shared(Bs + st * G_BS);
        uint32_t a_base = a_sh +
            (((wm * 64 + (lane & 15)) * 72) + (lane >> 4) * 8) * 2;
        uint32_t b_base = b_sh +
            (((wn * 64 + (lane & 7)) * 72) + ((lane >> 3) & 3) * 8) * 2;

#pragma unroll
        for (int kh = 0; kh < 2; kh++) {
            const uint32_t koff = kh * 32 * 2;
            uint32_t a[4][2][4];               // [mi][kb16][4]
#pragma unroll
            for (int mi = 0; mi < 4; mi++) {
                uint32_t ab = a_base + mi * 16 * 72 * 2 + koff;
                ldsm_x4(a[mi][0][0], a[mi][0][1], a[mi][0][2], a[mi][0][3], ab);
                ldsm_x4(a[mi][1][0], a[mi][1][1], a[mi][1][2], a[mi][1][3], ab + 32);
            }
#pragma unroll
            for (int ni = 0; ni < 8; ni++) {
                uint32_t b0, b1, b2, b3;
                ldsm_x4(b0, b1, b2, b3, b_base + ni * 8 * 72 * 2 + koff);
#pragma unroll
                for (int mi = 0; mi < 4; mi++) {
                    mma_bf16(acc[mi][ni], a[mi][0], b0, b1);
                    mma_bf16(acc[mi][ni], a[mi][1], b2, b3);
                }
            }
        }
    }

#pragma unroll
    for (int ni = 0; ni < 8; ni++) {
        int col = col0 + wn * 64 + ni * 8 + 2 * tq;
        float2 bv = *(const float2*)(bias + col);
#pragma unroll
        for (int mi = 0; mi < 4; mi++) {
            int rb = row0 + wm * 64 + mi * 16 + gq;
            if (OUT_BF16) {
                bf16* Cb = (bf16*)gb.C[z];
                *(uint32_t*)&Cb[(size_t)rb * 768 + col] =
                    bf16pack(acc[mi][ni][1] + bv.y, acc[mi][ni][0] + bv.x);
                *(uint32_t*)&Cb[(size_t)(rb + 8) * 768 + col] =
                    bf16pack(acc[mi][ni][3] + bv.y, acc[mi][ni][2] + bv.x);
            } else {
                float* Cf = (float*)gb.C[z];
                *(float2*)(Cf + (size_t)rb * 768 + col) =
                    make_float2(acc[mi][ni][0] + bv.x, acc[mi][ni][1] + bv.y);
                *(float2*)(Cf + (size_t)(rb + 8) * 768 + col) =
                    make_float2(acc[mi][ni][2] + bv.x, acc[mi][ni][3] + bv.y);
            }
        }
    }
}

// ---------------------------------------------------------------------------
// Flash attention bf16 — frozen R10 configuration (308 us).
// ---------------------------------------------------------------------------
struct FlashArgs {
    const bf16* Q[2]; const bf16* K[2]; const bf16* V[2];
    const float* mask[2]; bf16* O[2];
};

__global__ void __launch_bounds__(128, 3) flash_bf16_kernel(FlashArgs fa) {
    __shared__ __align__(16) bf16 Ks[2][64 * 72];
    __shared__ __align__(16) bf16 Vs[2][64 * 72];

    const int tid = threadIdx.x;
    const int warp = tid >> 5, lane = tid & 31;
    const int gq = lane >> 2, tq = lane & 3;
    const int sel = blockIdx.z >> 2, b = blockIdx.z & 3;
    const int h = blockIdx.y;
    const int q0 = blockIdx.x * 128;
    const int r0 = warp * 32;

    const bf16* Kbase = fa.K[sel] + ((size_t)(b * S)) * HID + h * HD;
    const bf16* Vbase = fa.V[sel] + ((size_t)(b * S)) * HID + h * HD;
    const float* mb = fa.mask[sel] + (size_t)b * S;

    const int lr = tid >> 3, lc = (tid & 7) << 3;

    auto load_kv = [&](int st, int k0) {
        const bf16* Kg = Kbase + (size_t)k0 * HID;
        const bf16* Vg = Vbase + (size_t)k0 * HID;
#pragma unroll
        for (int i = 0; i < 4; i++) {
            int r = lr + i * 16;
            cp16(&Ks[st][r * 72 + lc], Kg + (size_t)r * HID + lc);
            cp16(&Vs[st][r * 72 + lc], Vg + (size_t)r * HID + lc);
        }
    };

    uint32_t qf[2][4][4];
#pragma unroll
    for (int mt = 0; mt < 2; mt++) {
        const bf16* Qb = fa.Q[sel] +
            ((size_t)(b * S + q0 + r0 + mt * 16)) * HID + h * HD;
#pragma unroll
        for (int kb = 0; kb < 4; kb++) {
            int kk = kb * 16;
            qf[mt][kb][0] = *(const uint32_t*)&Qb[(size_t)gq * HID + kk + 2 * tq];
            qf[mt][kb][1] = *(const uint32_t*)&Qb[(size_t)(8 + gq) * HID + kk + 2 * tq];
            qf[mt][kb][2] = *(const uint32_t*)&Qb[(size_t)gq * HID + kk + 8 + 2 * tq];
            qf[mt][kb][3] = *(const uint32_t*)&Qb[(size_t)(8 + gq) * HID + kk + 8 + 2 * tq];
        }
    }

    const float C1 = 0.125f * 1.4426950408889634f;
    const float LOG2E = 1.4426950408889634f;

    float l0_lo = 0.f, l0_hi = 0.f, l1_lo = 0.f, l1_hi = 0.f;
    float o[2][8][4] = {};

    load_kv(0, 0);
    cp_commit();

    constexpr int NIT = S / 64;
    for (int it = 0; it < NIT; it++) {
        cp_wait0();
        __syncthreads();
        if (it + 1 < NIT) {
            load_kv((it + 1) & 1, (it + 1) * 64);
            cp_commit();
        }
        const int k0 = it * 64;

        uint32_t p0l[8], p0h[8], p1l[8], p1h[8];
        {
            uint32_t k_sh = (uint32_t)__cvta_generic_to_shared(Ks[it & 1]);
            uint32_t base = k_sh +
                (((lane & 7) * 72) + ((lane >> 3) & 3) * 8) * 2;
#pragma unroll
            for (int nf = 0; nf < 8; nf++) {
                uint32_t addr = base + nf * 8 * 72 * 2;
                uint32_t b0, b1, b2, b3, b4, b5, b6, b7;
                ldsm_x4(b0, b1, b2, b3, addr);
                ldsm_x4(b4, b5, b6, b7, addr + 64);
                float s0[4] = {}, s1[4] = {};
                mma_bf16(s0, qf[0][0], b0, b1);
                mma_bf16(s1, qf[1][0], b0, b1);
                mma_bf16(s0, qf[0][1], b2, b3);
                mma_bf16(s1, qf[1][1], b2, b3);
                mma_bf16(s0, qf[0][2], b4, b5);
                mma_bf16(s1, qf[1][2], b4, b5);
                mma_bf16(s0, qf[0][3], b6, b7);
                mma_bf16(s1, qf[1][3], b6, b7);

                float2 mv = *(const float2*)(mb + k0 + nf * 8 + 2 * tq);
                float mvx = mv.x * LOG2E, mvy = mv.y * LOG2E;
                float a0 = ex2(fmaf(s0[0], C1, mvx));
                float a1 = ex2(fmaf(s0[1], C1, mvy));
                float a2 = ex2(fmaf(s0[2], C1, mvx));
                float a3 = ex2(fmaf(s0[3], C1, mvy));
                l0_lo += a0 + a1; l0_hi += a2 + a3;
                p0l[nf] = bf16pack(a1, a0);
                p0h[nf] = bf16pack(a3, a2);
                float c0 = ex2(fmaf(s1[0], C1, mvx));
                float c1 = ex2(fmaf(s1[1], C1, mvy));
                float c2 = ex2(fmaf(s1[2], C1, mvx));
                float c3 = ex2(fmaf(s1[3], C1, mvy));
                l1_lo += c0 + c1; l1_hi += c2 + c3;
                p1l[nf] = bf16pack(c1, c0);
                p1h[nf] = bf16pack(c3, c2);
            }
        }

        {
            uint32_t v_sh = (uint32_t)__cvta_generic_to_shared(Vs[it & 1]);
            uint32_t base = v_sh +
                (((((lane >> 3) & 1) * 8 + (lane & 7)) * 72) + (lane >> 4) * 8) * 2;
#pragma unroll
            for (int j = 0; j < 4; j++) {
                uint32_t a0[4] = {p0l[2 * j], p0h[2 * j], p0l[2 * j + 1], p0h[2 * j + 1]};
                uint32_t a1[4] = {p1l[2 * j], p1h[2 * j], p1l[2 * j + 1], p1h[2 * j + 1]};
                uint32_t rowbase = base + j * 16 * 72 * 2;
#pragma unroll
                for (int nfp = 0; nfp < 4; nfp++) {
                    uint32_t b0, b1, b2, b3;
                    ldsm_x4_trans(b0, b1, b2, b3, rowbase + nfp * 32);
                    mma_bf16(o[0][2 * nfp], a0, b0, b1);
                    mma_bf16(o[0][2 * nfp + 1], a0, b2, b3);
                    mma_bf16(o[1][2 * nfp], a1, b0, b1);
                    mma_bf16(o[1][2 * nfp + 1], a1, b2, b3);
                }
            }
        }
    }

    l0_lo += __shfl_xor_sync(0xffffffffu, l0_lo, 1);
    l0_lo += __shfl_xor_sync(0xffffffffu, l0_lo, 2);
    l0_hi += __shfl_xor_sync(0xffffffffu, l0_hi, 1);
    l0_hi += __shfl_xor_sync(0xffffffffu, l0_hi, 2);
    l1_lo += __shfl_xor_sync(0xffffffffu, l1_lo, 1);
    l1_lo += __shfl_xor_sync(0xffffffffu, l1_lo, 2);
    l1_hi += __shfl_xor_sync(0xffffffffu, l1_hi, 1);
    l1_hi += __shfl_xor_sync(0xffffffffu, l1_hi, 2);

    float inv[2][2] = {{1.f / l0_lo, 1.f / l0_hi}, {1.f / l1_lo, 1.f / l1_hi}};
#pragma unroll
    for (int mt = 0; mt < 2; mt++) {
        bf16* Ob = fa.O[sel] +
            ((size_t)(b * S + q0 + r0 + mt * 16)) * HID + h * HD;
#pragma unroll
        for (int nf = 0; nf < 8; nf++) {
            int col = nf * 8 + 2 * tq;
            *(uint32_t*)&Ob[(size_t)gq * HID + col] =
                bf16pack(o[mt][nf][1] * inv[mt][0], o[mt][nf][0] * inv[mt][0]);
            *(uint32_t*)&Ob[(size_t)(8 + gq) * HID + col] =
                bf16pack(o[mt][nf][3] * inv[mt][1], o[mt][nf][2] * inv[mt][1]);
        }
    }
}

// ---------------------------------------------------------------------------
// out = LayerNorm(T + residual) * g + b. Warp per row, float4, no smem.
// ---------------------------------------------------------------------------
__global__ void __launch_bounds__(256) add_ln_kernel(
    const float* __restrict__ T1, const float* __restrict__ R1,
    const float* __restrict__ g1, const float* __restrict__ b1,
    float* __restrict__ o1,
    const float* __restrict__ T2, const float* __restrict__ R2,
    const float* __restrict__ g2, const float* __restrict__ b2,
    float* __restrict__ o2)
{
    const int st = blockIdx.y;
    const float* T = st ? T2 : T1;
    const float* R = st ? R2 : R1;
    const float* g = st ? g2 : g1;
    const float* bb = st ? b2 : b1;
    float* out = st ? o2 : o1;

    const int warp = threadIdx.x >> 5, lane = threadIdx.x & 31;
    const int row = blockIdx.x * 8 + warp;
    const float* Tr = T + (size_t)row * 768;
    const float* Rr = R + (size_t)row * 768;

    float4 x[6];
    float sum = 0.f, sq = 0.f;
#pragma unroll
    for (int j = 0; j < 6; j++) {
        int c = (j * 32 + lane) * 4;
        float4 t = *(const float4*)(Tr + c);
        float4 r = *(const float4*)(Rr + c);
        x[j] = make_float4(t.x + r.x, t.y + r.y, t.z + r.z, t.w + r.w);
        sum += x[j].x + x[j].y + x[j].z + x[j].w;
        sq += x[j].x * x[j].x + x[j].y * x[j].y +
              x[j].z * x[j].z + x[j].w * x[j].w;
    }
#pragma unroll
    for (int off = 16; off; off >>= 1) {
        sum += __shfl_xor_sync(0xffffffffu, sum, off);
        sq  += __shfl_xor_sync(0xffffffffu, sq,  off);
    }
    float mu = sum * (1.f / 768.f);
    float var = sq * (1.f / 768.f) - mu * mu;
    float rstd = rsqrtf(var + 1e-12f);
#pragma unroll
    for (int j = 0; j < 6; j++) {
        int c = (j * 32 + lane) * 4;
        float4 gv = *(const float4*)(g + c);
        float4 bv = *(const float4*)(bb + c);
        float4 ov;
        ov.x = (x[j].x - mu) * rstd * gv.x + bv.x;
        ov.y = (x[j].y - mu) * rstd * gv.y + bv.y;
        ov.z = (x[j].z - mu) * rstd * gv.z + bv.z;
        ov.w = (x[j].w - mu) * rstd * gv.w + bv.w;
        *(float4*)(out + (size_t)row * 768 + c) = ov;
    }
}

// ---------------------------------------------------------------------------
extern "C" void kernel_launch(void* const* d_in, const int* in_sizes, int n_in,
                              void* d_out, int out_size)
{
    const float* x1    = (const float*)d_in[0];
    const float* mask1 = (const float*)d_in[1];
    const float* x2    = (const float*)d_in[2];
    const float* mask2 = (const float*)d_in[3];
    const float* q1w = (const float*)d_in[4];  const float* q1b = (const float*)d_in[5];
    const float* k1w = (const float*)d_in[6];  const float* k1b = (const float*)d_in[7];
    const float* v1w = (const float*)d_in[8];  const float* v1b = (const float*)d_in[9];
    const float* q2w = (const float*)d_in[10]; const float* q2b = (const float*)d_in[11];
    const float* k2w = (const float*)d_in[12]; const float* k2b = (const float*)d_in[13];
    const float* v2w = (const float*)d_in[14]; const float* v2b = (const float*)d_in[15];
    const float* d1w = (const float*)d_in[16]; const float* d1b = (const float*)d_in[17];
    const float* d2w = (const float*)d_in[18]; const float* d2b = (const float*)d_in[19];
    const float* ln1g = (const float*)d_in[20]; const float* ln1b = (const float*)d_in[21];
    const float* ln2g = (const float*)d_in[22]; const float* ln2b = (const float*)d_in[23];

    void* sp = nullptr;
    cudaGetSymbolAddress(&sp, g_scratch);
    bf16* hb = (bf16*)sp;
    bf16* xb1  = hb + 0 * MAT;
    bf16* xb2  = hb + 1 * MAT;
    bf16* q1   = hb + 2 * MAT;
    bf16* k1   = hb + 3 * MAT;
    bf16* v1   = hb + 4 * MAT;
    bf16* q2   = hb + 5 * MAT;
    bf16* k2   = hb + 6 * MAT;
    bf16* v2   = hb + 7 * MAT;
    bf16* ctx1 = hb + 8 * MAT;
    bf16* ctx2 = hb + 9 * MAT;
    bf16* Wt   = hb + 10 * MAT;                  // 8 x 768 x 768 bf16
    float* t1  = (float*)(hb + 10 * MAT + 8 * 768 * 768);
    float* t2  = t1 + MAT;

    float* out1 = (float*)d_out;
    float* out2 = out1 + MAT;

    // converts
    conv_x_kernel<<<dim3(1024, 2), 256>>>(x1, x2, xb1, xb2);
    WPtrs wp;
    wp.w[0] = q1w; wp.w[1] = k1w; wp.w[2] = v1w;
    wp.w[3] = q2w; wp.w[4] = k2w; wp.w[5] = v2w;
    wp.w[6] = d1w; wp.w[7] = d2w;
    conv_wt_kernel<<<dim3(24, 24, 8), 256>>>(wp, Wt);

    const size_t WSZ = (size_t)768 * 768;

    cudaFuncSetAttribute(gemm_bf16_kernel<true>,
                         cudaFuncAttributeMaxDynamicSharedMemorySize, GEMM_SMEM);
    cudaFuncSetAttribute(gemm_bf16_kernel<false>,
                         cudaFuncAttributeMaxDynamicSharedMemorySize, GEMM_SMEM);

    // 6 input projections, bf16 out
    GemmBatch proj;
    proj.A[0] = xb1; proj.W[0] = Wt + 0 * WSZ; proj.bias[0] = q1b; proj.C[0] = q1;
    proj.A[1] = xb1; proj.W[1] = Wt + 1 * WSZ; proj.bias[1] = k1b; proj.C[1] = k1;
    proj.A[2] = xb1; proj.W[2] = Wt + 2 * WSZ; proj.bias[2] = v1b; proj.C[2] = v1;
    proj.A[3] = xb2; proj.W[3] = Wt + 3 * WSZ; proj.bias[3] = q2b; proj.C[3] = q2;
    proj.A[4] = xb2; proj.W[4] = Wt + 4 * WSZ; proj.bias[4] = k2b; proj.C[4] = k2;
    proj.A[5] = xb2; proj.W[5] = Wt + 5 * WSZ; proj.bias[5] = v2b; proj.C[5] = v2;
    gemm_bf16_kernel<true><<<dim3(6, 64, 6), 128, GEMM_SMEM>>>(proj);

    // both attention streams (128 threads/CTA, m32 warp tile)
    FlashArgs fa;
    fa.Q[0] = q2; fa.K[0] = k1; fa.V[0] = v1; fa.mask[0] = mask1; fa.O[0] = ctx1;
    fa.Q[1] = q1; fa.K[1] = k2; fa.V[1] = v2; fa.mask[1] = mask2; fa.O[1] = ctx2;
    flash_bf16_kernel<<<dim3(S / 128, H, 8), 128>>>(fa);

    // 2 output projections, f32 out
    GemmBatch dp;
    dp.A[0] = ctx1; dp.W[0] = Wt + 6 * WSZ; dp.bias[0] = d1b; dp.C[0] = t1;
    dp.A[1] = ctx2; dp.W[1] = Wt + 7 * WSZ; dp.bias[1] = d2b; dp.C[1] = t2;
    for (int i = 2; i < 6; i++) {
        dp.A[i] = nullptr; dp.W[i] = nullptr; dp.bias[i] = nullptr; dp.C[i] = nullptr;
    }
    gemm_bf16_kernel<false><<<dim3(6, 64, 2), 128, GEMM_SMEM>>>(dp);

    add_ln_kernel<<<dim3(M / 8, 2), 256>>>(t1, x1, ln1g, ln1b, out1,
                                           t2, x2, ln2g, ln2b, out2);
}

// round 15
// speedup vs baseline: 1.0145x; 1.0145x over previous
#include <cuda_runtime.h>
#include <cuda_bf16.h>
#include <cstdint>

// ---------------------------------------------------------------------------
// BertBiAttention — round 14: GEMM reverted to R12 config (best known);
// add_ln/conv_x get streaming cache hints. B=4,S=2048,HID=768,H=12.
// ---------------------------------------------------------------------------

constexpr int B = 4, S = 2048, HID = 768, H = 12, HD = 64;
constexpr int M = B * S;                       // 8192
constexpr size_t MAT = (size_t)M * HID;        // 6.29M elems

__device__ float g_scratch[10 * 6291456];

using bf16 = __nv_bfloat16;

__device__ __forceinline__ void cp16(void* dst_smem, const void* src) {
    uint32_t d = (uint32_t)__cvta_generic_to_shared(dst_smem);
    asm volatile("cp.async.cg.shared.global [%0], [%1], 16;" :: "r"(d), "l"(src));
}
__device__ __forceinline__ void cp_commit() { asm volatile("cp.async.commit_group;"); }
__device__ __forceinline__ void cp_wait0()  { asm volatile("cp.async.wait_group 0;"); }

__device__ __forceinline__ void mma_bf16(float c[4], const uint32_t a[4],
                                         uint32_t b0, uint32_t b1) {
    asm volatile(
        "mma.sync.aligned.m16n8k16.row.col.f32.bf16.bf16.f32 "
        "{%0,%1,%2,%3}, {%4,%5,%6,%7}, {%8,%9}, {%0,%1,%2,%3};"
        : "+f"(c[0]), "+f"(c[1]), "+f"(c[2]), "+f"(c[3])
        : "r"(a[0]), "r"(a[1]), "r"(a[2]), "r"(a[3]), "r"(b0), "r"(b1));
}

__device__ __forceinline__ uint32_t bf16pack(float hi, float lo) {
    uint32_t r;
    asm("cvt.rn.bf16x2.f32 %0, %1, %2;" : "=r"(r) : "f"(hi), "f"(lo));
    return r;
}

__device__ __forceinline__ float ex2(float x) {
    float r;
    asm("ex2.approx.ftz.f32 %0, %1;" : "=f"(r) : "f"(x));
    return r;
}

__device__ __forceinline__ void ldsm_x4(uint32_t& r0, uint32_t& r1,
                                        uint32_t& r2, uint32_t& r3,
                                        uint32_t smem_addr) {
    asm volatile("ldmatrix.sync.aligned.m8n8.x4.shared.b16 {%0,%1,%2,%3}, [%4];"
                 : "=r"(r0), "=r"(r1), "=r"(r2), "=r"(r3) : "r"(smem_addr));
}
__device__ __forceinline__ void ldsm_x4_trans(uint32_t& r0, uint32_t& r1,
                                              uint32_t& r2, uint32_t& r3,
                                              uint32_t smem_addr) {
    asm volatile("ldmatrix.sync.aligned.m8n8.x4.trans.shared.b16 {%0,%1,%2,%3}, [%4];"
                 : "=r"(r0), "=r"(r1), "=r"(r2), "=r"(r3) : "r"(smem_addr));
}

// streaming (evict-first) 128-bit load/store
__device__ __forceinline__ float4 ldg_cs4(const float* p) {
    float4 v;
    asm volatile("ld.global.cs.v4.f32 {%0,%1,%2,%3}, [%4];"
                 : "=f"(v.x), "=f"(v.y), "=f"(v.z), "=f"(v.w) : "l"(p));
    return v;
}
__device__ __forceinline__ void stg_cs4(float* p, float4 v) {
    asm volatile("st.global.cs.v4.f32 [%0], {%1,%2,%3,%4};"
                 :: "l"(p), "f"(v.x), "f"(v.y), "f"(v.z), "f"(v.w));
}

// ---------------------------------------------------------------------------
// Converters
// ---------------------------------------------------------------------------
__global__ void __launch_bounds__(256) conv_x_kernel(
    const float* __restrict__ x1, const float* __restrict__ x2,
    bf16* __restrict__ o1, bf16* __restrict__ o2)
{
    const float* x = blockIdx.y ? x2 : x1;
    bf16* o = blockIdx.y ? o2 : o1;
    const int n4 = (int)(MAT / 4);
    for (int i = blockIdx.x * 256 + threadIdx.x; i < n4; i += gridDim.x * 256) {
        float4 v = ldg_cs4(x + (size_t)i * 4);
        uint32_t lo = bf16pack(v.y, v.x);
        uint32_t hi = bf16pack(v.w, v.z);
        *(uint2*)(o + (size_t)i * 4) = make_uint2(lo, hi);
    }
}

struct WPtrs { const float* w[8]; };

// Wt[z][n][k] = bf16(W[z][k][n])
__global__ void __launch_bounds__(256) conv_wt_kernel(WPtrs wp, bf16* __restrict__ Wt) {
    __shared__ float t[32][33];
    const int z = blockIdx.z;
    const float* W = wp.w[z];
    const int k0 = blockIdx.x * 32, n0 = blockIdx.y * 32;
    const int tx = threadIdx.x & 31, ty = threadIdx.x >> 5;   // 32 x 8
#pragma unroll
    for (int r = 0; r < 4; r++)
        t[ty + r * 8][tx] = W[(size_t)(k0 + ty + r * 8) * 768 + n0 + tx];
    __syncthreads();
    bf16* O = Wt + (size_t)z * 768 * 768;
#pragma unroll
    for (int r = 0; r < 4; r++)
        O[(size_t)(n0 + ty + r * 8) * 768 + k0 + tx] =
            __float2bfloat16(t[tx][ty + r * 8]);
}

// ---------------------------------------------------------------------------
// Batched GEMM bf16 — EXACT R12 config (best known): BM=128, BN=128, BK=64,
// 8 warps (4m x 2n), warp tile 32x64, ldmatrix, launch_bounds(256,2).
// ---------------------------------------------------------------------------
struct GemmBatch {
    const bf16* A[6]; const bf16* W[6]; const float* bias[6]; void* C[6];
};

constexpr int G_AS = 128 * 72;
constexpr int G_BS = 128 * 72;
constexpr int GEMM_SMEM = (2 * G_AS + 2 * G_BS) * 2;   // 73728 B

template <bool OUT_BF16>
__global__ void __launch_bounds__(256, 2) gemm_bf16_kernel(GemmBatch gb) {
    const int z = blockIdx.z;
    const bf16* A = gb.A[z];
    const bf16* W = gb.W[z];
    const float* bias = gb.bias[z];

    extern __shared__ __align__(16) bf16 smg[];
    bf16* As = smg;
    bf16* Bs = smg + 2 * G_AS;

    const int tid = threadIdx.x;
    const int warp = tid >> 5, lane = tid & 31;
    const int gq = lane >> 2, tq = lane & 3;
    const int wm = warp & 3, wn = warp >> 2;
    const int row0 = blockIdx.y * 128, col0 = blockIdx.x * 128;

    const int r8 = tid >> 3, c8 = (tid & 7) << 3;

    auto load_tile = [&](int st, int k0) {
        bf16* Ab = As + st * G_AS;
        bf16* Bb = Bs + st * G_BS;
#pragma unroll
        for (int i = 0; i < 4; i++) {
            int r = r8 + i * 32;
            cp16(&Ab[r * 72 + c8], A + (size_t)(row0 + r) * 768 + k0 + c8);
            cp16(&Bb[r * 72 + c8], W + (size_t)(col0 + r) * 768 + k0 + c8);
        }
    };

    float acc[2][8][4] = {};

    load_tile(0, 0);
    cp_commit();

    for (int kt = 0; kt < 12; kt++) {
        cp_wait0();
        __syncthreads();
        if (kt + 1 < 12) {
            load_tile((kt + 1) & 1, (kt + 1) * 64);
            cp_commit();
        }
        const int st = kt & 1;
        uint32_t a_sh = (uint32_t)__cvta_generic_to_shared(As + st * G_AS);
        uint32_t b_sh = (uint32_t)__cvta_generic_to_shared(Bs + st * G_BS);
        uint32_t a_base = a_sh +
            (((wm * 32 + (lane & 15)) * 72) + (lane >> 4) * 8) * 2;
        uint32_t b_base = b_sh +
            (((wn * 64 + (lane & 7)) * 72) + ((lane >> 3) & 3) * 8) * 2;

#pragma unroll
        for (int kh = 0; kh < 2; kh++) {
            const uint32_t koff = kh * 32 * 2;
            uint32_t a[2][2][4];
#pragma unroll
            for (int mi = 0; mi < 2; mi++) {
                uint32_t ab = a_base + mi * 16 * 72 * 2 + koff;
                ldsm_x4(a[mi][0][0], a[mi][0][1], a[mi][0][2], a[mi][0][3], ab);
                ldsm_x4(a[mi][1][0], a[mi][1][1], a[mi][1][2], a[mi][1][3], ab + 32);
            }
#pragma unroll
            for (int ni = 0; ni < 8; ni++) {
                uint32_t b0, b1, b2, b3;
                ldsm_x4(b0, b1, b2, b3, b_base + ni * 8 * 72 * 2 + koff);
#pragma unroll
                for (int mi = 0; mi < 2; mi++) {
                    mma_bf16(acc[mi][ni], a[mi][0], b0, b1);
                    mma_bf16(acc[mi][ni], a[mi][1], b2, b3);
                }
            }
        }
    }

#pragma unroll
    for (int ni = 0; ni < 8; ni++) {
        int col = col0 + wn * 64 + ni * 8 + 2 * tq;
        float2 bv = *(const float2*)(bias + col);
#pragma unroll
        for (int mi = 0; mi < 2; mi++) {
            int rb = row0 + wm * 32 + mi * 16 + gq;
            if (OUT_BF16) {
                bf16* Cb = (bf16*)gb.C[z];
                *(uint32_t*)&Cb[(size_t)rb * 768 + col] =
                    bf16pack(acc[mi][ni][1] + bv.y, acc[mi][ni][0] + bv.x);
                *(uint32_t*)&Cb[(size_t)(rb + 8) * 768 + col] =
                    bf16pack(acc[mi][ni][3] + bv.y, acc[mi][ni][2] + bv.x);
            } else {
                float* Cf = (float*)gb.C[z];
                *(float2*)(Cf + (size_t)rb * 768 + col) =
                    make_float2(acc[mi][ni][0] + bv.x, acc[mi][ni][1] + bv.y);
                *(float2*)(Cf + (size_t)(rb + 8) * 768 + col) =
                    make_float2(acc[mi][ni][2] + bv.x, acc[mi][ni][3] + bv.y);
            }
        }
    }
}

// ---------------------------------------------------------------------------
// Flash attention bf16 — frozen R10 configuration (308 us).
// ---------------------------------------------------------------------------
struct FlashArgs {
    const bf16* Q[2]; const bf16* K[2]; const bf16* V[2];
    const float* mask[2]; bf16* O[2];
};

__global__ void __launch_bounds__(128, 3) flash_bf16_kernel(FlashArgs fa) {
    __shared__ __align__(16) bf16 Ks[2][64 * 72];
    __shared__ __align__(16) bf16 Vs[2][64 * 72];

    const int tid = threadIdx.x;
    const int warp = tid >> 5, lane = tid & 31;
    const int gq = lane >> 2, tq = lane & 3;
    const int sel = blockIdx.z >> 2, b = blockIdx.z & 3;
    const int h = blockIdx.y;
    const int q0 = blockIdx.x * 128;
    const int r0 = warp * 32;

    const bf16* Kbase = fa.K[sel] + ((size_t)(b * S)) * HID + h * HD;
    const bf16* Vbase = fa.V[sel] + ((size_t)(b * S)) * HID + h * HD;
    const float* mb = fa.mask[sel] + (size_t)b * S;

    const int lr = tid >> 3, lc = (tid & 7) << 3;

    auto load_kv = [&](int st, int k0) {
        const bf16* Kg = Kbase + (size_t)k0 * HID;
        const bf16* Vg = Vbase + (size_t)k0 * HID;
#pragma unroll
        for (int i = 0; i < 4; i++) {
            int r = lr + i * 16;
            cp16(&Ks[st][r * 72 + lc], Kg + (size_t)r * HID + lc);
            cp16(&Vs[st][r * 72 + lc], Vg + (size_t)r * HID + lc);
        }
    };

    uint32_t qf[2][4][4];
#pragma unroll
    for (int mt = 0; mt < 2; mt++) {
        const bf16* Qb = fa.Q[sel] +
            ((size_t)(b * S + q0 + r0 + mt * 16)) * HID + h * HD;
#pragma unroll
        for (int kb = 0; kb < 4; kb++) {
            int kk = kb * 16;
            qf[mt][kb][0] = *(const uint32_t*)&Qb[(size_t)gq * HID + kk + 2 * tq];
            qf[mt][kb][1] = *(const uint32_t*)&Qb[(size_t)(8 + gq) * HID + kk + 2 * tq];
            qf[mt][kb][2] = *(const uint32_t*)&Qb[(size_t)gq * HID + kk + 8 + 2 * tq];
            qf[mt][kb][3] = *(const uint32_t*)&Qb[(size_t)(8 + gq) * HID + kk + 8 + 2 * tq];
        }
    }

    const float C1 = 0.125f * 1.4426950408889634f;
    const float LOG2E = 1.4426950408889634f;

    float l0_lo = 0.f, l0_hi = 0.f, l1_lo = 0.f, l1_hi = 0.f;
    float o[2][8][4] = {};

    load_kv(0, 0);
    cp_commit();

    constexpr int NIT = S / 64;
    for (int it = 0; it < NIT; it++) {
        cp_wait0();
        __syncthreads();
        if (it + 1 < NIT) {
            load_kv((it + 1) & 1, (it + 1) * 64);
            cp_commit();
        }
        const int k0 = it * 64;

        uint32_t p0l[8], p0h[8], p1l[8], p1h[8];
        {
            uint32_t k_sh = (uint32_t)__cvta_generic_to_shared(Ks[it & 1]);
            uint32_t base = k_sh +
                (((lane & 7) * 72) + ((lane >> 3) & 3) * 8) * 2;
#pragma unroll
            for (int nf = 0; nf < 8; nf++) {
                uint32_t addr = base + nf * 8 * 72 * 2;
                uint32_t b0, b1, b2, b3, b4, b5, b6, b7;
                ldsm_x4(b0, b1, b2, b3, addr);
                ldsm_x4(b4, b5, b6, b7, addr + 64);
                float s0[4] = {}, s1[4] = {};
                mma_bf16(s0, qf[0][0], b0, b1);
                mma_bf16(s1, qf[1][0], b0, b1);
                mma_bf16(s0, qf[0][1], b2, b3);
                mma_bf16(s1, qf[1][1], b2, b3);
                mma_bf16(s0, qf[0][2], b4, b5);
                mma_bf16(s1, qf[1][2], b4, b5);
                mma_bf16(s0, qf[0][3], b6, b7);
                mma_bf16(s1, qf[1][3], b6, b7);

                float2 mv = *(const float2*)(mb + k0 + nf * 8 + 2 * tq);
                float mvx = mv.x * LOG2E, mvy = mv.y * LOG2E;
                float a0 = ex2(fmaf(s0[0], C1, mvx));
                float a1 = ex2(fmaf(s0[1], C1, mvy));
                float a2 = ex2(fmaf(s0[2], C1, mvx));
                float a3 = ex2(fmaf(s0[3], C1, mvy));
                l0_lo += a0 + a1; l0_hi += a2 + a3;
                p0l[nf] = bf16pack(a1, a0);
                p0h[nf] = bf16pack(a3, a2);
                float c0 = ex2(fmaf(s1[0], C1, mvx));
                float c1 = ex2(fmaf(s1[1], C1, mvy));
                float c2 = ex2(fmaf(s1[2], C1, mvx));
                float c3 = ex2(fmaf(s1[3], C1, mvy));
                l1_lo += c0 + c1; l1_hi += c2 + c3;
                p1l[nf] = bf16pack(c1, c0);
                p1h[nf] = bf16pack(c3, c2);
            }
        }

        {
            uint32_t v_sh = (uint32_t)__cvta_generic_to_shared(Vs[it & 1]);
            uint32_t base = v_sh +
                (((((lane >> 3) & 1) * 8 + (lane & 7)) * 72) + (lane >> 4) * 8) * 2;
#pragma unroll
            for (int j = 0; j < 4; j++) {
                uint32_t a0[4] = {p0l[2 * j], p0h[2 * j], p0l[2 * j + 1], p0h[2 * j + 1]};
                uint32_t a1[4] = {p1l[2 * j], p1h[2 * j], p1l[2 * j + 1], p1h[2 * j + 1]};
                uint32_t rowbase = base + j * 16 * 72 * 2;
#pragma unroll
                for (int nfp = 0; nfp < 4; nfp++) {
                    uint32_t b0, b1, b2, b3;
                    ldsm_x4_trans(b0, b1, b2, b3, rowbase + nfp * 32);
                    mma_bf16(o[0][2 * nfp], a0, b0, b1);
                    mma_bf16(o[0][2 * nfp + 1], a0, b2, b3);
                    mma_bf16(o[1][2 * nfp], a1, b0, b1);
                    mma_bf16(o[1][2 * nfp + 1], a1, b2, b3);
                }
            }
        }
    }

    l0_lo += __shfl_xor_sync(0xffffffffu, l0_lo, 1);
    l0_lo += __shfl_xor_sync(0xffffffffu, l0_lo, 2);
    l0_hi += __shfl_xor_sync(0xffffffffu, l0_hi, 1);
    l0_hi += __shfl_xor_sync(0xffffffffu, l0_hi, 2);
    l1_lo += __shfl_xor_sync(0xffffffffu, l1_lo, 1);
    l1_lo += __shfl_xor_sync(0xffffffffu, l1_lo, 2);
    l1_hi += __shfl_xor_sync(0xffffffffu, l1_hi, 1);
    l1_hi += __shfl_xor_sync(0xffffffffu, l1_hi, 2);

    float inv[2][2] = {{1.f / l0_lo, 1.f / l0_hi}, {1.f / l1_lo, 1.f / l1_hi}};
#pragma unroll
    for (int mt = 0; mt < 2; mt++) {
        bf16* Ob = fa.O[sel] +
            ((size_t)(b * S + q0 + r0 + mt * 16)) * HID + h * HD;
#pragma unroll
        for (int nf = 0; nf < 8; nf++) {
            int col = nf * 8 + 2 * tq;
            *(uint32_t*)&Ob[(size_t)gq * HID + col] =
                bf16pack(o[mt][nf][1] * inv[mt][0], o[mt][nf][0] * inv[mt][0]);
            *(uint32_t*)&Ob[(size_t)(8 + gq) * HID + col] =
                bf16pack(o[mt][nf][3] * inv[mt][1], o[mt][nf][2] * inv[mt][1]);
        }
    }
}

// ---------------------------------------------------------------------------
// out = LayerNorm(T + residual) * g + b. Warp per row; streaming ld/st
// (all operands read-once, output never re-read).
// ---------------------------------------------------------------------------
__global__ void __launch_bounds__(256) add_ln_kernel(
    const float* __restrict__ T1, const float* __restrict__ R1,
    const float* __restrict__ g1, const float* __restrict__ b1,
    float* __restrict__ o1,
    const float* __restrict__ T2, const float* __restrict__ R2,
    const float* __restrict__ g2, const float* __restrict__ b2,
    float* __restrict__ o2)
{
    const int st = blockIdx.y;
    const float* T = st ? T2 : T1;
    const float* R = st ? R2 : R1;
    const float* g = st ? g2 : g1;
    const float* bb = st ? b2 : b1;
    float* out = st ? o2 : o1;

    const int warp = threadIdx.x >> 5, lane = threadIdx.x & 31;
    const int row = blockIdx.x * 8 + warp;
    const float* Tr = T + (size_t)row * 768;
    const float* Rr = R + (size_t)row * 768;

    float4 x[6];
    float sum = 0.f, sq = 0.f;
#pragma unroll
    for (int j = 0; j < 6; j++) {
        int c = (j * 32 + lane) * 4;
        float4 t = ldg_cs4(Tr + c);
        float4 r = ldg_cs4(Rr + c);
        x[j] = make_float4(t.x + r.x, t.y + r.y, t.z + r.z, t.w + r.w);
        sum += x[j].x + x[j].y + x[j].z + x[j].w;
        sq += x[j].x * x[j].x + x[j].y * x[j].y +
              x[j].z * x[j].z + x[j].w * x[j].w;
    }
#pragma unroll
    for (int off = 16; off; off >>= 1) {
        sum += __shfl_xor_sync(0xffffffffu, sum, off);
        sq  += __shfl_xor_sync(0xffffffffu, sq,  off);
    }
    float mu = sum * (1.f / 768.f);
    float var = sq * (1.f / 768.f) - mu * mu;
    float rstd = rsqrtf(var + 1e-12f);
#pragma unroll
    for (int j = 0; j < 6; j++) {
        int c = (j * 32 + lane) * 4;
        float4 gv = *(const float4*)(g + c);
        float4 bv = *(const float4*)(bb + c);
        float4 ov;
        ov.x = (x[j].x - mu) * rstd * gv.x + bv.x;
        ov.y = (x[j].y - mu) * rstd * gv.y + bv.y;
        ov.z = (x[j].z - mu) * rstd * gv.z + bv.z;
        ov.w = (x[j].w - mu) * rstd * gv.w + bv.w;
        stg_cs4(out + (size_t)row * 768 + c, ov);
    }
}

// ---------------------------------------------------------------------------
extern "C" void kernel_launch(void* const* d_in, const int* in_sizes, int n_in,
                              void* d_out, int out_size)
{
    const float* x1    = (const float*)d_in[0];
    const float* mask1 = (const float*)d_in[1];
    const float* x2    = (const float*)d_in[2];
    const float* mask2 = (const float*)d_in[3];
    const float* q1w = (const float*)d_in[4];  const float* q1b = (const float*)d_in[5];
    const float* k1w = (const float*)d_in[6];  const float* k1b = (const float*)d_in[7];
    const float* v1w = (const float*)d_in[8];  const float* v1b = (const float*)d_in[9];
    const float* q2w = (const float*)d_in[10]; const float* q2b = (const float*)d_in[11];
    const float* k2w = (const float*)d_in[12]; const float* k2b = (const float*)d_in[13];
    const float* v2w = (const float*)d_in[14]; const float* v2b = (const float*)d_in[15];
    const float* d1w = (const float*)d_in[16]; const float* d1b = (const float*)d_in[17];
    const float* d2w = (const float*)d_in[18]; const float* d2b = (const float*)d_in[19];
    const float* ln1g = (const float*)d_in[20]; const float* ln1b = (const float*)d_in[21];
    const float* ln2g = (const float*)d_in[22]; const float* ln2b = (const float*)d_in[23];

    void* sp = nullptr;
    cudaGetSymbolAddress(&sp, g_scratch);
    bf16* hb = (bf16*)sp;
    bf16* xb1  = hb + 0 * MAT;
    bf16* xb2  = hb + 1 * MAT;
    bf16* q1   = hb + 2 * MAT;
    bf16* k1   = hb + 3 * MAT;
    bf16* v1   = hb + 4 * MAT;
    bf16* q2   = hb + 5 * MAT;
    bf16* k2   = hb + 6 * MAT;
    bf16* v2   = hb + 7 * MAT;
    bf16* ctx1 = hb + 8 * MAT;
    bf16* ctx2 = hb + 9 * MAT;
    bf16* Wt   = hb + 10 * MAT;                  // 8 x 768 x 768 bf16
    float* t1  = (float*)(hb + 10 * MAT + 8 * 768 * 768);
    float* t2  = t1 + MAT;

    float* out1 = (float*)d_out;
    float* out2 = out1 + MAT;

    // converts
    conv_x_kernel<<<dim3(1024, 2), 256>>>(x1, x2, xb1, xb2);
    WPtrs wp;
    wp.w[0] = q1w; wp.w[1] = k1w; wp.w[2] = v1w;
    wp.w[3] = q2w; wp.w[4] = k2w; wp.w[5] = v2w;
    wp.w[6] = d1w; wp.w[7] = d2w;
    conv_wt_kernel<<<dim3(24, 24, 8), 256>>>(wp, Wt);

    const size_t WSZ = (size_t)768 * 768;

    cudaFuncSetAttribute(gemm_bf16_kernel<true>,
                         cudaFuncAttributeMaxDynamicSharedMemorySize, GEMM_SMEM);
    cudaFuncSetAttribute(gemm_bf16_kernel<false>,
                         cudaFuncAttributeMaxDynamicSharedMemorySize, GEMM_SMEM);

    // 6 input projections, bf16 out
    GemmBatch proj;
    proj.A[0] = xb1; proj.W[0] = Wt + 0 * WSZ; proj.bias[0] = q1b; proj.C[0] = q1;
    proj.A[1] = xb1; proj.W[1] = Wt + 1 * WSZ; proj.bias[1] = k1b; proj.C[1] = k1;
    proj.A[2] = xb1; proj.W[2] = Wt + 2 * WSZ; proj.bias[2] = v1b; proj.C[2] = v1;
    proj.A[3] = xb2; proj.W[3] = Wt + 3 * WSZ; proj.bias[3] = q2b; proj.C[3] = q2;
    proj.A[4] = xb2; proj.W[4] = Wt + 4 * WSZ; proj.bias[4] = k2b; proj.C[4] = k2;
    proj.A[5] = xb2; proj.W[5] = Wt + 5 * WSZ; proj.bias[5] = v2b; proj.C[5] = v2;
    gemm_bf16_kernel<true><<<dim3(6, 64, 6), 256, GEMM_SMEM>>>(proj);

    // both attention streams (128 threads/CTA, m32 warp tile)
    FlashArgs fa;
    fa.Q[0] = q2; fa.K[0] = k1; fa.V[0] = v1; fa.mask[0] = mask1; fa.O[0] = ctx1;
    fa.Q[1] = q1; fa.K[1] = k2; fa.V[1] = v2; fa.mask[1] = mask2; fa.O[1] = ctx2;
    flash_bf16_kernel<<<dim3(S / 128, H, 8), 128>>>(fa);

    // 2 output projections, f32 out
    GemmBatch dp;
    dp.A[0] = ctx1; dp.W[0] = Wt + 6 * WSZ; dp.bias[0] = d1b; dp.C[0] = t1;
    dp.A[1] = ctx2; dp.W[1] = Wt + 7 * WSZ; dp.bias[1] = d2b; dp.C[1] = t2;
    for (int i = 2; i < 6; i++) {
        dp.A[i] = nullptr; dp.W[i] = nullptr; dp.bias[i] = nullptr; dp.C[i] = nullptr;
    }
    gemm_bf16_kernel<false><<<dim3(6, 64, 2), 256, GEMM_SMEM>>>(dp);

    add_ln_kernel<<<dim3(M / 8, 2), 256>>>(t1, x1, ln1g, ln1b, out1,
                                           t2, x2, ln2g, ln2b, out2);
}